// round 8
// baseline (speedup 1.0000x reference)
#include <cuda_runtime.h>
#include <math.h>

// inv+1 map: flat rep id -> (AO row + 1); 0 = hole. Zero-init at module load;
// hole slots never written; scatter collision-free & replay-idempotent.
__device__ int g_inv1[16384];

__global__ void scatter_inv_kernel(const int* __restrict__ ids, int n_ao) {
    int t = blockIdx.x * blockDim.x + threadIdx.x;
    if (t < n_ao) g_inv1[ids[t]] = t + 1;
}

// out[a1][a2][r1][r2] = feat[inv[a1*14+r1]][inv[a2*14+r2]]  (0 on hole)
//
// Block = a1 (500 blocks). Loop over chunks of 32 a2 atoms:
//  Gather phase: warp w (0..13) owns r1=w -> ONE feat row. Lanes cover
//   2 atoms x 14 r2 (lane>>4 = atom pair, lane&15 = r2). All 28 loads of a
//   warp fall in ~120 contiguous bytes of that row -> 1-2 L1 wavefronts.
//   Values land in smem tile already in OUTPUT layout (atom stride 208
//   floats; 208 % 32 == 16 -> the two atoms' lanes hit disjoint banks).
//  Flush phase: 512 threads store the tile as fully coalesced float4 STG.
#define CHUNK 32
#define ATS   208          // atom stride in tile (196 data + 12 pad)

__global__ __launch_bounds__(512) void gather_kernel(
    const float* __restrict__ feat,
    float4* __restrict__ out,
    unsigned n_ao, unsigned n_atoms) {

    __shared__ float tile[CHUNK * ATS];      // 26624 B
    __shared__ short s_inv[8192];            // inv+1 as int16 (values <= 5801)

    const unsigned tid = threadIdx.x;
    const unsigned total = n_atoms * 14u;
    for (unsigned t = tid; t < total; t += 512u)
        s_inv[t] = (short)g_inv1[t];
    __syncthreads();

    const unsigned a1  = blockIdx.x;
    const unsigned wid = tid >> 5;           // warp 0..15 (0..13 gather)
    const unsigned r2  = tid & 15u;          // lane&15
    const unsigned pair = (tid & 31u) >> 4;  // 0/1: which atom of the pair
    const bool g_act = (wid < 14u) && (r2 < 14u);

    // fixed per-warp feat row
    const unsigned r1 = wid;
    int i1 = 0;
    if (wid < 14u) i1 = s_inv[a1 * 14u + r1];
    const bool okr = (i1 > 0);
    const float* frow = feat + (size_t)(i1 - 1) * n_ao;

    for (unsigned a2_lo = 0; a2_lo < n_atoms; a2_lo += CHUNK) {
        const unsigned nA2 = min((unsigned)CHUNK, n_atoms - a2_lo);

        // ── gather (warp-coherent LDG, permuted STS) ──
        if (g_act) {
            const unsigned nP = (nA2 + 1u) >> 1;
            for (unsigned p = 0; p < nP; ++p) {
                const unsigned a2l = 2u * p + pair;
                if (a2l < nA2) {
                    const int j = s_inv[(a2_lo + a2l) * 14u + r2];
                    float v = 0.0f;
                    if (okr && j > 0) v = __ldg(frow + (unsigned)(j - 1));
                    tile[a2l * ATS + r1 * 14u + r2] = v;
                }
            }
        }
        __syncthreads();

        // ── flush (coalesced float4) ──
        const unsigned nV = nA2 * 49u;
        float4* dst = out + ((size_t)a1 * n_atoms + a2_lo) * 49u;
        for (unsigned idx = tid; idx < nV; idx += 512u) {
            const unsigned a2l = idx / 49u;           // const div
            const unsigned q   = idx - a2l * 49u;
            dst[idx] = *(const float4*)(tile + a2l * ATS + q * 4u);
        }
        __syncthreads();
    }
}

extern "C" void kernel_launch(void* const* d_in, const int* in_sizes, int n_in,
                              void* d_out, int out_size) {
    const float* feat = (const float*)d_in[0];
    const int*   ids  = (const int*)d_in[1];

    const int n_ao = in_sizes[1];               // 5800
    const int R    = 14;                        // num_reps_1d
    const int a2r  = out_size / (R * R);        // A^2
    const int A    = (int)(sqrtf((float)a2r) + 0.5f);   // 500

    scatter_inv_kernel<<<(n_ao + 255) / 256, 256>>>(ids, n_ao);
    gather_kernel<<<A, 512>>>(feat, (float4*)d_out,
                              (unsigned)n_ao, (unsigned)A);
}

// round 9
// speedup vs baseline: 2.0120x; 2.0120x over previous
#include <cuda_runtime.h>
#include <math.h>

// inv+1 map: flat rep id -> (AO row + 1); 0 = hole. Zero-init at module load;
// hole slots never written; scatter collision-free & replay-idempotent.
__device__ int g_inv1[16384];

__global__ void scatter_inv_kernel(const int* __restrict__ ids, int n_ao) {
    int t = blockIdx.x * blockDim.x + threadIdx.x;
    if (t < n_ao) g_inv1[ids[t]] = t + 1;
}

// out[a1][a2][r1][r2] = feat[inv[a1*14+r1]][inv[a2*14+r2]]  (0 on hole)
//
// Grid = (2, A): blockIdx.y = a1, blockIdx.x picks half the a2 range.
// Per 32-atom chunk:
//  Gather: warp w<14 owns r1=w -> ONE feat row; lanes = 2 atoms x 14 r2, so a
//   warp's LDG spans ~120 contiguous bytes (1-2 wavefronts). Fully unrolled
//   batches of 8 (LDS x8 -> LDG x8 -> STS x8) give MLP=8 per warp; chunk size
//   is a compile-time 32 (s_inv zero-padded -> out-of-range atoms read holes).
//   STS layout = output layout (atom stride 208; 208%32=16 -> the two atoms'
//   lanes hit disjoint banks).
//  Flush: 512 threads store the tile as fully coalesced float4 STG.
#define CHUNK 32
#define ATS   208          // atom stride in tile (196 data + 12 pad)

__global__ __launch_bounds__(512) void gather_kernel(
    const float* __restrict__ feat,
    float4* __restrict__ out,
    unsigned n_ao, unsigned n_atoms, unsigned half) {

    __shared__ float tile[CHUNK * ATS];      // 26624 B
    __shared__ short s_inv[7680];            // inv+1 as int16, zero-padded

    const unsigned tid = threadIdx.x;
    for (unsigned t = tid; t < 7680u; t += 512u)
        s_inv[t] = (short)g_inv1[t];         // g_inv1 zero beyond used range
    __syncthreads();

    const unsigned a1   = blockIdx.y;
    const unsigned base = blockIdx.x * half;
    const unsigned aEnd = min(base + half, n_atoms);

    const unsigned lane = tid & 31u;
    const unsigned wid  = tid >> 5;          // 0..15 (0..13 gather)
    const unsigned r2   = lane & 15u;
    const unsigned pair = lane >> 4;         // 0/1: which atom of the pair
    const bool g_act = (wid < 14u) && (r2 < 14u);

    const unsigned r1 = wid;
    const int i1 = (wid < 14u) ? (int)s_inv[a1 * 14u + r1] : 0;
    const bool okr = (i1 > 0);
    const float* frow = feat + (size_t)(i1 - 1) * n_ao;
    const unsigned sts_base = r1 * 14u + r2; // fixed within-atom offset

    for (unsigned a2_lo = base; a2_lo < aEnd; a2_lo += CHUNK) {
        // ── gather: compile-time 32 atoms, MLP-8 batches ──
        if (g_act) {
            const unsigned ibase = a2_lo * 14u + r2;
#pragma unroll
            for (int pb = 0; pb < 2; ++pb) {
                int   jj[8];
                float vv[8];
#pragma unroll
                for (int p = 0; p < 8; ++p) {
                    const unsigned a2l = 2u * (unsigned)(pb * 8 + p) + pair;
                    jj[p] = (int)s_inv[ibase + a2l * 14u];
                }
#pragma unroll
                for (int p = 0; p < 8; ++p) {
                    float v = 0.0f;
                    if (okr && jj[p] > 0) v = __ldg(frow + (unsigned)(jj[p] - 1));
                    vv[p] = v;
                }
#pragma unroll
                for (int p = 0; p < 8; ++p) {
                    const unsigned a2l = 2u * (unsigned)(pb * 8 + p) + pair;
                    tile[a2l * ATS + sts_base] = vv[p];
                }
            }
        }
        __syncthreads();

        // ── flush: coalesced float4 stores for the valid atoms ──
        const unsigned nA2 = min((unsigned)CHUNK, aEnd - a2_lo);
        const unsigned nV  = nA2 * 49u;
        float4* dst = out + ((size_t)a1 * n_atoms + a2_lo) * 49u;
        for (unsigned idx = tid; idx < nV; idx += 512u) {
            const unsigned a2l = idx / 49u;          // const mul-shift
            const unsigned q   = idx - a2l * 49u;
            dst[idx] = *(const float4*)(tile + a2l * ATS + q * 4u);
        }
        __syncthreads();
    }
}

extern "C" void kernel_launch(void* const* d_in, const int* in_sizes, int n_in,
                              void* d_out, int out_size) {
    const float* feat = (const float*)d_in[0];
    const int*   ids  = (const int*)d_in[1];

    const int n_ao = in_sizes[1];               // 5800
    const int R    = 14;                        // num_reps_1d
    const int a2r  = out_size / (R * R);        // A^2
    const int A    = (int)(sqrtf((float)a2r) + 0.5f);   // 500
    const unsigned half = (unsigned)((A + 1) / 2);      // 250

    scatter_inv_kernel<<<(n_ao + 255) / 256, 256>>>(ids, n_ao);

    dim3 grid(2, (unsigned)A);                  // 1000 blocks
    gather_kernel<<<grid, 512>>>(feat, (float4*)d_out,
                                 (unsigned)n_ao, (unsigned)A, half);
}

// round 10
// speedup vs baseline: 2.1221x; 1.0547x over previous
#include <cuda_runtime.h>
#include <math.h>

// out[a1][a2][r1][r2] = feat[inv[a1*14+r1]][inv[a2*14+r2]]  (0 on hole)
//
// Single kernel. Grid = (2, A): blockIdx.y = a1, blockIdx.x = half of a2 range.
// Each block rebuilds inv+1 (0 = hole) in smem from ids (23 KB, L2-resident).
// Per 32-atom chunk, software-pipelined:
//   gather(next) -> 16 independent LDG into regs (warp w<14 owns r1=w -> one
//   feat row, lanes = 2 atoms x 14 r2 -> ~120 contiguous bytes per LDG);
//   STS(cur) into tile in OUTPUT layout (atom stride 208; 208%32=16 ->
//   conflict-free); sync; flush(cur) via precomputed per-thread float4 slots;
//   sync. LDG latency of chunk n+1 hides under STS+flush of chunk n.
#define CHUNK 32
#define ATS   208
#define NT    512

__global__ __launch_bounds__(NT, 2) void gather_kernel(
    const float* __restrict__ feat,
    float4* __restrict__ out,
    const int* __restrict__ ids,
    unsigned n_ao, unsigned n_atoms, unsigned half) {

    __shared__ float tile[CHUNK * ATS];      // 26624 B
    __shared__ short s_inv[7680];            // inv+1 as int16, zero-padded

    const unsigned tid = threadIdx.x;
    for (unsigned t = tid; t < 7680u; t += NT) s_inv[t] = 0;
    __syncthreads();
    for (unsigned t = tid; t < n_ao; t += NT) s_inv[ids[t]] = (short)(t + 1);
    __syncthreads();

    const unsigned a1   = blockIdx.y;
    const unsigned base = blockIdx.x * half;
    const unsigned aEnd = min(base + half, n_atoms);

    const unsigned lane = tid & 31u;
    const unsigned wid  = tid >> 5;          // 0..15 (0..13 gather)
    const unsigned r2   = lane & 15u;
    const unsigned pair = lane >> 4;         // which atom of the lane pair
    const bool g_act = (wid < 14u) && (r2 < 14u);

    const unsigned r1 = wid;
    const int i1 = (wid < 14u) ? (int)s_inv[a1 * 14u + r1] : 0;
    const bool okr = (i1 > 0);               // warp-uniform
    const float* frow = feat + (size_t)(i1 - 1) * n_ao;
    const unsigned sts_base = r1 * 14u + r2;

    // chunk-invariant flush slots: out idx = tid + k*512, tile offset fixed
    unsigned tOff[4], oIdx[4];
#pragma unroll
    for (int k = 0; k < 4; ++k) {
        const unsigned idx = tid + (unsigned)k * NT;
        const unsigned a2l = idx / 49u;      // const mul-shift
        const unsigned q   = idx - a2l * 49u;
        tOff[k] = a2l * ATS + q * 4u;
        oIdx[k] = idx;                       // k=3 valid only for tid<32
    }

    float vv[16];
    // prologue: gather chunk at `base`
    if (g_act) {
        if (okr) {
            const unsigned ibase = base * 14u + r2;
            int jj[16];
#pragma unroll
            for (int p = 0; p < 16; ++p)
                jj[p] = (int)s_inv[ibase + (2u * (unsigned)p + pair) * 14u];
#pragma unroll
            for (int p = 0; p < 16; ++p) {
                float v = 0.0f;
                if (jj[p] > 0) v = __ldg(frow + (unsigned)(jj[p] - 1));
                vv[p] = v;
            }
        } else {
#pragma unroll
            for (int p = 0; p < 16; ++p) vv[p] = 0.0f;
        }
    }

    for (unsigned a2_lo = base; a2_lo < aEnd; a2_lo += CHUNK) {
        const unsigned nxt = a2_lo + CHUNK;

        // ── pipelined gather of NEXT chunk (LDGs in flight during flush) ──
        float vn[16];
        if (nxt < aEnd && g_act) {
            if (okr) {
                const unsigned ibase = nxt * 14u + r2;
                int jj[16];
#pragma unroll
                for (int p = 0; p < 16; ++p)
                    jj[p] = (int)s_inv[ibase + (2u * (unsigned)p + pair) * 14u];
#pragma unroll
                for (int p = 0; p < 16; ++p) {
                    float v = 0.0f;
                    if (jj[p] > 0) v = __ldg(frow + (unsigned)(jj[p] - 1));
                    vn[p] = v;
                }
            } else {
#pragma unroll
                for (int p = 0; p < 16; ++p) vn[p] = 0.0f;
            }
        }

        // ── STS current chunk into output-layout tile ──
        if (g_act) {
#pragma unroll
            for (int p = 0; p < 16; ++p)
                tile[(2u * (unsigned)p + pair) * ATS + sts_base] = vv[p];
        }
        __syncthreads();

        // ── flush: coalesced float4 stores, precomputed slots ──
        const unsigned nV = min((unsigned)CHUNK, aEnd - a2_lo) * 49u;
        float4* dst = out + ((size_t)a1 * n_atoms + a2_lo) * 49u;
#pragma unroll
        for (int k = 0; k < 4; ++k)
            if (oIdx[k] < nV)
                dst[oIdx[k]] = *(const float4*)(tile + tOff[k]);
        __syncthreads();

#pragma unroll
        for (int p = 0; p < 16; ++p) vv[p] = vn[p];
    }
}

extern "C" void kernel_launch(void* const* d_in, const int* in_sizes, int n_in,
                              void* d_out, int out_size) {
    const float* feat = (const float*)d_in[0];
    const int*   ids  = (const int*)d_in[1];

    const int n_ao = in_sizes[1];               // 5800
    const int R    = 14;                        // num_reps_1d
    const int a2r  = out_size / (R * R);        // A^2
    const int A    = (int)(sqrtf((float)a2r) + 0.5f);   // 500
    const unsigned half = (unsigned)((A + 1) / 2);      // 250

    dim3 grid(2, (unsigned)A);                  // 1000 blocks
    gather_kernel<<<grid, NT>>>(feat, (float4*)d_out, ids,
                                (unsigned)n_ao, (unsigned)A, half);
}

// round 12
// speedup vs baseline: 2.3700x; 1.1168x over previous
#include <cuda_runtime.h>
#include <math.h>

// inv+1 map: flat rep id -> (AO row + 1); 0 = hole. Zero-init at module load;
// hole slots never written; scatter collision-free & replay-idempotent.
__device__ int g_inv1[16384];

__global__ void scatter_inv_kernel(const int* __restrict__ ids, int n_ao) {
    int t = blockIdx.x * blockDim.x + threadIdx.x;
    if (t < n_ao) g_inv1[ids[t]] = t + 1;
}

// out[a1][a2][r1][r2] = feat[inv[a1*14+r1]][inv[a2*14+r2]]  (0 on hole)
//
// Warp-autonomous: each warp owns (a1, strip of 32 a2) and a private smem
// 2-tile slot; NO block-wide barriers. Lane = (dr, r2): dr = lane/14 (2 rows
// per pass), r2 = lane%14; 7 passes cover r1 = 0..13. Per 2-atom iteration:
// 2 inv LDG (L1-hot) + 14 independent feat LDG (MLP 14) + 14 STS
// (conflict-free) + float4 flush, separated only by __syncwarp().
// Row bases precomputed per warp via 7 shuffles. NOTE: base+j added in
// unsigned 32-bit BEFORE pointer arithmetic (wraps back correctly; the
// unparenthesized form faults for AO row 0).
#define G_STRIP 32
#define WARPS_PB 4
#define TW 200               // floats per tile slot (196 + pad, 16B-aligned)

__global__ __launch_bounds__(128) void gather_kernel(
    const float* __restrict__ feat,
    float4* __restrict__ out,
    unsigned n_ao, unsigned n_atoms) {

    __shared__ float tw[WARPS_PB * 2 * TW];          // 6.4 KB

    const unsigned tid  = threadIdx.x;
    const unsigned lane = tid & 31u;
    const unsigned wid  = tid >> 5;
    const unsigned a1   = blockIdx.x;
    const unsigned strip = blockIdx.y * WARPS_PB + wid;
    const unsigned s0 = strip * G_STRIP;
    if (s0 >= n_atoms) return;                        // warp-uniform
    const unsigned s1 = min(s0 + G_STRIP, n_atoms);

    const unsigned dr = lane / 14u;                   // 0,1 (2 for idle lanes)
    const unsigned r2 = lane - dr * 14u;
    const bool act = lane < 28u;

    // per-warp row bases: base[p] for r1 = 2p+dr, built from 7 shuffles
    int i1v = 0;
    if (lane < 14u) i1v = g_inv1[a1 * 14u + lane];
    unsigned base[7]; bool ok[7];
#pragma unroll
    for (int p = 0; p < 7; ++p) {
        const int iv = __shfl_sync(0xffffffffu, i1v, (int)(2u * (unsigned)p + dr));
        ok[p]   = act && (iv > 0);
        base[p] = (unsigned)(iv - 1) * n_ao - 1u;     // u32; +j wraps back
    }

    float* mytile = tw + wid * (2u * TW);
    const float4* t4 = (const float4*)mytile;         // tile1 at float4 idx 50

    for (unsigned a2 = s0; a2 < s1; a2 += 2u) {
        const bool two = (a2 + 1u) < s1;
        unsigned j0 = 0, j1 = 0;
        if (act) {
            j0 = (unsigned)__ldg(&g_inv1[a2 * 14u + r2]);
            if (two) j1 = (unsigned)__ldg(&g_inv1[(a2 + 1u) * 14u + r2]);
        }

        float v0[7], v1[7];
#pragma unroll
        for (int p = 0; p < 7; ++p) {
            float x = 0.0f;
            if (ok[p] && j0 > 0u) x = __ldg(feat + (base[p] + j0));
            v0[p] = x;
        }
#pragma unroll
        for (int p = 0; p < 7; ++p) {
            float x = 0.0f;
            if (ok[p] && j1 > 0u) x = __ldg(feat + (base[p] + j1));
            v1[p] = x;
        }

        if (act) {
#pragma unroll
            for (int p = 0; p < 7; ++p) {
                const unsigned off = (2u * (unsigned)p + dr) * 14u + r2;
                mytile[off]      = v0[p];
                mytile[TW + off] = v1[p];
            }
        }
        __syncwarp();

        // flush: tiles are contiguous 49-float4 blocks in out
        float4* dst = out + ((size_t)a1 * n_atoms + a2) * 49u;
        dst[lane] = t4[lane];
        if (lane < 17u) dst[32u + lane] = t4[32u + lane];
        if (two) {
            dst[49u + lane] = t4[50u + lane];
            if (lane < 17u) dst[81u + lane] = t4[82u + lane];
        }
        __syncwarp();
    }
}

extern "C" void kernel_launch(void* const* d_in, const int* in_sizes, int n_in,
                              void* d_out, int out_size) {
    const float* feat = (const float*)d_in[0];
    const int*   ids  = (const int*)d_in[1];

    const int n_ao = in_sizes[1];               // 5800
    const int R    = 14;                        // num_reps_1d
    const int a2r  = out_size / (R * R);        // A^2
    const int A    = (int)(sqrtf((float)a2r) + 0.5f);   // 500

    scatter_inv_kernel<<<(n_ao + 255) / 256, 256>>>(ids, n_ao);

    const unsigned nstrips = ((unsigned)A + G_STRIP - 1u) / G_STRIP;   // 16
    dim3 grid((unsigned)A, (nstrips + WARPS_PB - 1u) / WARPS_PB);      // 500 x 4
    gather_kernel<<<grid, 128>>>(feat, (float4*)d_out,
                                 (unsigned)n_ao, (unsigned)A);
}

// round 14
// speedup vs baseline: 2.4424x; 1.0306x over previous
#include <cuda_runtime.h>
#include <math.h>

// inv+1 map: flat rep id -> (AO row + 1); 0 = hole. Zero-init at module load;
// hole slots never written; scatter collision-free & replay-idempotent.
__device__ int g_inv1[16384];

__global__ void scatter_inv_kernel(const int* __restrict__ ids, int n_ao) {
    int t = blockIdx.x * blockDim.x + threadIdx.x;
    if (t < n_ao) g_inv1[ids[t]] = t + 1;
}

// out[a1][a2][r1][r2] = feat[inv[a1*14+r1]][inv[a2*14+r2]]  (0 on hole)
//
// Warp-autonomous, NO shared memory in the hot loop. Lane = (dr, r2):
// dr = lane/14, r2 = lane%14 (28 active). For pass p, lane holds the value of
// tile offset (2p+dr)*14 + r2 = 28p + lane -> the 28 lanes are a CONTIGUOUS
// 112 B output span: direct coalesced STG.32, no smem transpose, no syncwarp.
// Iterations are fully independent -> compiler software-pipelines (unroll 2
// gives 28 feat LDGs in flight per warp).
#define G_STRIP 32
#define WARPS_PB 4

__global__ __launch_bounds__(128) void gather_kernel(
    const float* __restrict__ feat,
    float* __restrict__ out,
    unsigned n_ao, unsigned n_atoms) {

    const unsigned lane = threadIdx.x & 31u;
    const unsigned wid  = threadIdx.x >> 5;
    const unsigned a1   = blockIdx.x;
    const unsigned strip = blockIdx.y * WARPS_PB + wid;
    const unsigned s0 = strip * G_STRIP;
    if (s0 >= n_atoms) return;                        // warp-uniform
    const unsigned s1 = min(s0 + G_STRIP, n_atoms);

    const unsigned dr = lane / 14u;                   // 0,1 (2 = idle lanes)
    const unsigned r2 = lane - dr * 14u;
    const bool act = lane < 28u;

    // per-warp row bases for r1 = 2p+dr via 7 shuffles
    int i1v = 0;
    if (lane < 14u) i1v = g_inv1[a1 * 14u + lane];
    unsigned base[7]; bool ok[7];
#pragma unroll
    for (int p = 0; p < 7; ++p) {
        const int iv = __shfl_sync(0xffffffffu, i1v, (int)(2u * (unsigned)p + dr));
        ok[p]   = act && (iv > 0);
        base[p] = (unsigned)(iv - 1) * n_ao - 1u;     // u32; (+j) wraps back
    }

    // out offset of tile (a1, s0), element `lane`
    float* dst = out + (size_t)((a1 * n_atoms + s0) * 196u + lane);

#pragma unroll 2
    for (unsigned a2 = s0; a2 < s1; a2 += 2u) {
        const bool two = (a2 + 1u) < s1;
        unsigned j0 = 0, j1 = 0;
        if (act) {
            j0 = (unsigned)__ldg(&g_inv1[a2 * 14u + r2]);
            if (two) j1 = (unsigned)__ldg(&g_inv1[(a2 + 1u) * 14u + r2]);
        }

        float v0[7], v1[7];
#pragma unroll
        for (int p = 0; p < 7; ++p) {
            float x = 0.0f;
            if (ok[p] && j0 > 0u) x = __ldg(feat + (base[p] + j0));
            v0[p] = x;
        }
#pragma unroll
        for (int p = 0; p < 7; ++p) {
            float x = 0.0f;
            if (ok[p] && j1 > 0u) x = __ldg(feat + (base[p] + j1));
            v1[p] = x;
        }

        if (act) {
#pragma unroll
            for (int p = 0; p < 7; ++p) dst[28u * (unsigned)p] = v0[p];
            if (two) {
#pragma unroll
                for (int p = 0; p < 7; ++p) dst[196u + 28u * (unsigned)p] = v1[p];
            }
        }
        dst += 392u;
    }
}

extern "C" void kernel_launch(void* const* d_in, const int* in_sizes, int n_in,
                              void* d_out, int out_size) {
    const float* feat = (const float*)d_in[0];
    const int*   ids  = (const int*)d_in[1];

    const int n_ao = in_sizes[1];               // 5800
    const int R    = 14;                        // num_reps_1d
    const int a2r  = out_size / (R * R);        // A^2
    const int A    = (int)(sqrtf((float)a2r) + 0.5f);   // 500

    scatter_inv_kernel<<<(n_ao + 255) / 256, 256>>>(ids, n_ao);

    const unsigned nstrips = ((unsigned)A + G_STRIP - 1u) / G_STRIP;   // 16
    dim3 grid((unsigned)A, (nstrips + WARPS_PB - 1u) / WARPS_PB);      // 500 x 4
    gather_kernel<<<grid, 128>>>(feat, (float*)d_out,
                                 (unsigned)n_ao, (unsigned)A);
}

// round 16
// speedup vs baseline: 2.4528x; 1.0042x over previous
#include <cuda_runtime.h>
#include <math.h>

// inv+1 map: flat rep id -> (AO row + 1); 0 = hole. Zero-init at module load;
// hole slots never written; scatter collision-free & replay-idempotent.
__device__ int g_inv1[16384];

__global__ void scatter_inv_kernel(const int* __restrict__ ids, int n_ao) {
    int t = blockIdx.x * blockDim.x + threadIdx.x;
    if (t < n_ao) g_inv1[ids[t]] = t + 1;
}

// out[a1][a2][r1][r2] = feat[inv[a1*14+r1]][inv[a2*14+r2]]  (0 on hole)
//
// Warp-autonomous, no smem. Lane = (dr, r2): dr = lane/14, r2 = lane%14
// (28 active). Pass p covers r1 = 2p+dr; lane's value lands at tile offset
// 28p+lane -> 28 lanes form a CONTIGUOUS 112 B span: coalesced STG.32.
// G_STRIP = 42 -> 12 strips -> grid 500x3 = 1500 blocks; at ~12 blocks/SM
// capacity (40 regs) this fits in ONE wave (capacity ~1776), eliminating the
// 2-wave tail that capped R13 at 61.5% occupancy.
#define G_STRIP 42
#define WARPS_PB 4

__global__ __launch_bounds__(128) void gather_kernel(
    const float* __restrict__ feat,
    float* __restrict__ out,
    unsigned n_ao, unsigned n_atoms) {

    const unsigned lane = threadIdx.x & 31u;
    const unsigned wid  = threadIdx.x >> 5;
    const unsigned a1   = blockIdx.x;
    const unsigned strip = blockIdx.y * WARPS_PB + wid;
    const unsigned s0 = strip * G_STRIP;
    if (s0 >= n_atoms) return;                        // warp-uniform
    const unsigned s1 = min(s0 + G_STRIP, n_atoms);

    const unsigned dr = lane / 14u;                   // 0,1 (2 = idle lanes)
    const unsigned r2 = lane - dr * 14u;
    const bool act = lane < 28u;

    // per-warp row bases for r1 = 2p+dr via 7 shuffles
    int i1v = 0;
    if (lane < 14u) i1v = g_inv1[a1 * 14u + lane];
    unsigned base[7]; bool ok[7];
#pragma unroll
    for (int p = 0; p < 7; ++p) {
        const int iv = __shfl_sync(0xffffffffu, i1v, (int)(2u * (unsigned)p + dr));
        ok[p]   = act && (iv > 0);
        base[p] = (unsigned)(iv - 1) * n_ao - 1u;     // u32; (+j) wraps back
    }

    float* dst = out + (size_t)((a1 * n_atoms + s0) * 196u + lane);

#pragma unroll 2
    for (unsigned a2 = s0; a2 < s1; a2 += 2u) {
        const bool two = (a2 + 1u) < s1;
        unsigned j0 = 0, j1 = 0;
        if (act) {
            j0 = (unsigned)__ldg(&g_inv1[a2 * 14u + r2]);
            if (two) j1 = (unsigned)__ldg(&g_inv1[(a2 + 1u) * 14u + r2]);
        }

        float v0[7], v1[7];
#pragma unroll
        for (int p = 0; p < 7; ++p) {
            float x = 0.0f;
            if (ok[p] && j0 > 0u) x = __ldg(feat + (base[p] + j0));
            v0[p] = x;
        }
#pragma unroll
        for (int p = 0; p < 7; ++p) {
            float x = 0.0f;
            if (ok[p] && j1 > 0u) x = __ldg(feat + (base[p] + j1));
            v1[p] = x;
        }

        if (act) {
#pragma unroll
            for (int p = 0; p < 7; ++p) dst[28u * (unsigned)p] = v0[p];
            if (two) {
#pragma unroll
                for (int p = 0; p < 7; ++p) dst[196u + 28u * (unsigned)p] = v1[p];
            }
        }
        dst += 392u;
    }
}

extern "C" void kernel_launch(void* const* d_in, const int* in_sizes, int n_in,
                              void* d_out, int out_size) {
    const float* feat = (const float*)d_in[0];
    const int*   ids  = (const int*)d_in[1];

    const int n_ao = in_sizes[1];               // 5800
    const int R    = 14;                        // num_reps_1d
    const int a2r  = out_size / (R * R);        // A^2
    const int A    = (int)(sqrtf((float)a2r) + 0.5f);   // 500

    scatter_inv_kernel<<<(n_ao + 255) / 256, 256>>>(ids, n_ao);

    const unsigned nstrips = ((unsigned)A + G_STRIP - 1u) / G_STRIP;   // 12
    dim3 grid((unsigned)A, (nstrips + WARPS_PB - 1u) / WARPS_PB);      // 500 x 3
    gather_kernel<<<grid, 128>>>(feat, (float*)d_out,
                                 (unsigned)n_ao, (unsigned)A);
}